// round 2
// baseline (speedup 1.0000x reference)
#include <cuda_runtime.h>
#include <cuda_fp16.h>
#include <cstdint>

#define NFEAT   2048
#define NBATCH  8192
#define NFIELDS 8
#define FDIM    256
#define NL      64
#define ROWT    128

// fp16 scratch (static device arrays -- no runtime allocation)
__device__ __half g_xh[(size_t)NBATCH * NFEAT];              // 32 MB, row-major [B, F]
__device__ __half g_vh[NFIELDS * NFIELDS * NL * FDIM];        // 2 MB, [s][t][l][k]

// ---------------- SMEM layout (dynamic) ----------------
// [0,1024):        dks (256 floats) for diagonal units
// X tiles: 4 chunks x [128 rows x 128B] each (chunk c holds k in [64c,64c+64))
// V tiles: 4 chunks x [64 rows x 128B]
#define SM_DKS  0
#define SM_X1   1024
#define SM_X2   (1024 + 65536)
#define SM_V1   (1024 + 131072)
#define SM_V2   (1024 + 131072 + 32768)
#define SM_TOTAL (1024 + 196608)  // 197632 B

#define SW128(off) ((off) ^ (((off) >> 3) & 0x70))

static __device__ __forceinline__ uint32_t smem_u32(const void* p) {
    uint32_t a;
    asm("{ .reg .u64 t; cvta.to.shared.u64 t, %1; cvt.u32.u64 %0, t; }" : "=r"(a) : "l"(p));
    return a;
}

static __device__ __forceinline__ void ldmx4(uint32_t addr, uint32_t& r0, uint32_t& r1,
                                             uint32_t& r2, uint32_t& r3) {
    asm volatile("ldmatrix.sync.aligned.m8n8.x4.shared.b16 {%0,%1,%2,%3}, [%4];"
                 : "=r"(r0), "=r"(r1), "=r"(r2), "=r"(r3) : "r"(addr));
}

static __device__ __forceinline__ void mma16816(float* d, uint32_t a0, uint32_t a1,
                                                uint32_t a2, uint32_t a3,
                                                uint32_t b0, uint32_t b1) {
    asm volatile(
        "mma.sync.aligned.m16n8k16.row.col.f32.f16.f16.f32 "
        "{%0,%1,%2,%3}, {%4,%5,%6,%7}, {%8,%9}, {%0,%1,%2,%3};"
        : "+f"(d[0]), "+f"(d[1]), "+f"(d[2]), "+f"(d[3])
        : "r"(a0), "r"(a1), "r"(a2), "r"(a3), "r"(b0), "r"(b1));
}

// unit table: 8 diagonal + 28 unordered pairs (s < t)
__device__ const signed char U_S[36] = {0,1,2,3,4,5,6,7,
    0,0,0,0,0,0,0, 1,1,1,1,1,1, 2,2,2,2,2, 3,3,3,3, 4,4,4, 5,5, 6};
__device__ const signed char U_T[36] = {0,1,2,3,4,5,6,7,
    1,2,3,4,5,6,7, 2,3,4,5,6,7, 3,4,5,6,7, 4,5,6,7, 5,6,7, 6,7, 7};

// ------------------------------------------------------------------
__global__ void k_convert_x(const float* __restrict__ x) {
    size_t i = (size_t)blockIdx.x * blockDim.x + threadIdx.x;
    size_t n2 = (size_t)NBATCH * NFEAT / 2;
    if (i < n2) {
        float2 f = ((const float2*)x)[i];
        ((__half2*)g_xh)[i] = __floats2half2_rn(f.x, f.y);
    }
}

__global__ void k_convert_v(const float* __restrict__ V) {
    int idx = blockIdx.x * blockDim.x + threadIdx.x;  // over 2048*8*64
    if (idx < NFEAT * NFIELDS * NL) {
        int i = idx / (NFIELDS * NL);
        int rest = idx % (NFIELDS * NL);
        int t = rest / NL, l = rest % NL;
        int s = i >> 8, k = i & 255;
        g_vh[(((s * NFIELDS + t) * NL) + l) * FDIM + k] = __float2half_rn(V[idx]);
    }
}

__global__ void k_init_out(const float* __restrict__ b, float* __restrict__ out) {
    int i = blockIdx.x * blockDim.x + threadIdx.x;
    if (i < NBATCH) out[i] = b[0];
}

// ------------------------------------------------------------------
// Accumulate D[16 rows x 64 cols] fragments for: X_tile(warp's 16 rows x 256) @ V_tile^T
// acc[nt][4]: n-tile nt covers cols nt*8..nt*8+7.
static __device__ __forceinline__ void gemm_warp(uint32_t sx, uint32_t sv,
                                                 int wid, int lane, float acc[8][4]) {
    const int arow = wid * 16 + (lane & 15);
    const int akoff8 = (lane >> 4) << 3;                 // 0 or 8 halves
    const int brow_base = ((lane >> 4) << 3) + (lane & 7);  // 0..15 pattern
    const int bkoff8 = ((lane >> 3) & 1) << 3;

    #pragma unroll 2
    for (int kt = 0; kt < 16; ++kt) {
        const int kbase = kt * 16;
        const int chunk = kbase >> 6;
        const int kin = kbase & 63;
        uint32_t a0, a1, a2, a3;
        uint32_t addrA = sx + chunk * 16384 + SW128(arow * 128 + (kin + akoff8) * 2);
        ldmx4(addrA, a0, a1, a2, a3);
        #pragma unroll
        for (int vt = 0; vt < 4; ++vt) {
            const int l0 = vt * 16;
            uint32_t b0, b1, b2, b3;
            uint32_t addrB = sv + chunk * 8192 +
                             SW128((l0 + brow_base) * 128 + (kin + bkoff8) * 2);
            ldmx4(addrB, b0, b1, b2, b3);
            mma16816(acc[2 * vt], a0, a1, a2, a3, b0, b1);
            mma16816(acc[2 * vt + 1], a0, a1, a2, a3, b2, b3);
        }
    }
}

__global__ __launch_bounds__(256, 1)
void ffm_main(const float* __restrict__ w, float* __restrict__ out) {
    extern __shared__ char smem[];
    const uint32_t sb = smem_u32(smem);
    const int tid = threadIdx.x;
    const int wid = tid >> 5;
    const int lane = tid & 31;
    const int r0 = blockIdx.x * ROWT;

    float acc_int0 = 0.f, acc_int1 = 0.f;   // 0.25-scaled later; rows wid*16+lane/4 (+8)
    float acc_lin0 = 0.f, acc_lin1 = 0.f;
    float* dks = (float*)(smem + SM_DKS);

    for (int uu = 0; uu < 4; ++uu) {
        const int u = blockIdx.y * 4 + uu;
        const int s = U_S[u], t = U_T[u];
        const bool diag = (s == t);

        // ---- cooperative tile loads (SW128, 4 chunks) ----
        {
            const uint4* src = (const uint4*)(g_xh + (size_t)r0 * NFEAT + s * FDIM);
            #pragma unroll 4
            for (int idx = tid; idx < ROWT * 32; idx += 256) {
                int row = idx >> 5, c = idx & 31;
                uint4 v = src[(size_t)row * (NFEAT / 8) + c];
                *(uint4*)(smem + SM_X1 + (c >> 3) * 16384 + SW128(row * 128 + (c & 7) * 16)) = v;
            }
        }
        if (!diag) {
            const uint4* src = (const uint4*)(g_xh + (size_t)r0 * NFEAT + t * FDIM);
            #pragma unroll 4
            for (int idx = tid; idx < ROWT * 32; idx += 256) {
                int row = idx >> 5, c = idx & 31;
                uint4 v = src[(size_t)row * (NFEAT / 8) + c];
                *(uint4*)(smem + SM_X2 + (c >> 3) * 16384 + SW128(row * 128 + (c & 7) * 16)) = v;
            }
        }
        {
            const uint4* src = (const uint4*)(g_vh + (size_t)((s * NFIELDS + t) * NL) * FDIM);
            #pragma unroll 2
            for (int idx = tid; idx < NL * 32; idx += 256) {
                int row = idx >> 5, c = idx & 31;
                uint4 v = src[row * 32 + c];
                *(uint4*)(smem + SM_V1 + (c >> 3) * 8192 + SW128(row * 128 + (c & 7) * 16)) = v;
            }
        }
        if (!diag) {
            const uint4* src = (const uint4*)(g_vh + (size_t)((t * NFIELDS + s) * NL) * FDIM);
            #pragma unroll 2
            for (int idx = tid; idx < NL * 32; idx += 256) {
                int row = idx >> 5, c = idx & 31;
                uint4 v = src[row * 32 + c];
                *(uint4*)(smem + SM_V2 + (c >> 3) * 8192 + SW128(row * 128 + (c & 7) * 16)) = v;
            }
        }
        __syncthreads();

        // ---- tensor-core GEMMs ----
        float accA[8][4], accB[8][4];
        #pragma unroll
        for (int n = 0; n < 8; ++n)
            #pragma unroll
            for (int j = 0; j < 4; ++j) { accA[n][j] = 0.f; accB[n][j] = 0.f; }

        gemm_warp(sb + SM_X1, sb + SM_V1, wid, lane, accA);
        if (!diag) gemm_warp(sb + SM_X2, sb + SM_V2, wid, lane, accB);

        // ---- epilogue ----
        float p0 = 0.f, p1 = 0.f;
        if (!diag) {
            #pragma unroll
            for (int n = 0; n < 8; ++n) {
                p0 += accA[n][0] * accB[n][0] + accA[n][1] * accB[n][1];
                p1 += accA[n][2] * accB[n][2] + accA[n][3] * accB[n][3];
            }
            p0 *= 2.f; p1 *= 2.f;
            p0 += __shfl_xor_sync(0xFFFFFFFFu, p0, 1);
            p0 += __shfl_xor_sync(0xFFFFFFFFu, p0, 2);
            p1 += __shfl_xor_sync(0xFFFFFFFFu, p1, 1);
            p1 += __shfl_xor_sync(0xFFFFFFFFu, p1, 2);
            acc_int0 += p0; acc_int1 += p1;
        } else {
            // q + linear from the SAME fp16 tiles the MMA consumed
            {
                int k = tid;  // 256 threads -> one k each
                float a = 0.f;
                int chunk = k >> 6, kk = (k & 63) * 2;
                #pragma unroll 8
                for (int l = 0; l < NL; ++l)
                    a += __half2float(*(const __half*)(smem + SM_V1 + chunk * 8192 +
                                                       SW128(l * 128 + kk))) *
                         __half2float(*(const __half*)(smem + SM_V1 + chunk * 8192 +
                                                       SW128(l * 128 + kk)));
                dks[k] = a;
            }
            __syncthreads();
            const int rloc0 = wid * 16 + (lane >> 2);
            const int rloc1 = rloc0 + 8;
            const int kseg = lane & 3;               // each of 4 lanes per row: 64 k's
            const float* wp = w + s * FDIM + kseg * 64;
            float q0 = 0.f, q1 = 0.f, l0 = 0.f, l1 = 0.f;
            #pragma unroll 8
            for (int kk = 0; kk < 64; ++kk) {
                int k = kseg * 64 + kk;
                float dk = dks[k];
                float wv = __ldg(wp + kk);
                float x0 = __half2float(*(const __half*)(smem + SM_X1 + kseg * 16384 +
                                                         SW128(rloc0 * 128 + kk * 2)));
                float x1 = __half2float(*(const __half*)(smem + SM_X1 + kseg * 16384 +
                                                         SW128(rloc1 * 128 + kk * 2)));
                q0 += x0 * x0 * dk; l0 += x0 * wv;
                q1 += x1 * x1 * dk; l1 += x1 * wv;
            }
            #pragma unroll
            for (int n = 0; n < 8; ++n) {
                p0 += accA[n][0] * accA[n][0] + accA[n][1] * accA[n][1];
                p1 += accA[n][2] * accA[n][2] + accA[n][3] * accA[n][3];
            }
            p0 -= q0; p1 -= q1;
            p0 += __shfl_xor_sync(0xFFFFFFFFu, p0, 1);
            p0 += __shfl_xor_sync(0xFFFFFFFFu, p0, 2);
            p1 += __shfl_xor_sync(0xFFFFFFFFu, p1, 1);
            p1 += __shfl_xor_sync(0xFFFFFFFFu, p1, 2);
            l0 += __shfl_xor_sync(0xFFFFFFFFu, l0, 1);
            l0 += __shfl_xor_sync(0xFFFFFFFFu, l0, 2);
            l1 += __shfl_xor_sync(0xFFFFFFFFu, l1, 1);
            l1 += __shfl_xor_sync(0xFFFFFFFFu, l1, 2);
            acc_int0 += p0; acc_int1 += p1;
            acc_lin0 += l0; acc_lin1 += l1;
        }
        __syncthreads();   // before next unit's loads overwrite tiles
    }

    if ((lane & 3) == 0) {
        int row = r0 + wid * 16 + (lane >> 2);
        atomicAdd(out + row,      acc_lin0 + 0.25f * acc_int0);
        atomicAdd(out + row + 8,  acc_lin1 + 0.25f * acc_int1);
    }
}

// ------------------------------------------------------------------
extern "C" void kernel_launch(void* const* d_in, const int* in_sizes, int n_in,
                              void* d_out, int out_size) {
    const float* x = (const float*)d_in[0];
    const float* b = (const float*)d_in[1];
    const float* w = (const float*)d_in[2];
    const float* V = (const float*)d_in[3];
    float* out = (float*)d_out;

    cudaFuncSetAttribute(ffm_main, cudaFuncAttributeMaxDynamicSharedMemorySize, SM_TOTAL);

    {
        size_t n2 = (size_t)NBATCH * NFEAT / 2;
        k_convert_x<<<(unsigned)((n2 + 255) / 256), 256>>>(x);
    }
    k_convert_v<<<(NFEAT * NFIELDS * NL + 255) / 256, 256>>>(V);
    k_init_out<<<(NBATCH + 255) / 256, 256>>>(b, out);
    ffm_main<<<dim3(NBATCH / ROWT, 9), 256, SM_TOTAL>>>(w, out);
}

// round 3
// speedup vs baseline: 1.3538x; 1.3538x over previous
#include <cuda_runtime.h>
#include <cuda_fp16.h>
#include <cstdint>

#define NFEAT   2048
#define NBATCH  8192
#define NFIELDS 8
#define FDIM    256
#define NL      64
#define ROWT    256
#define NTHREADS 512

// fp16 scratch (static device arrays -- no runtime allocation)
__device__ __half g_xh[(size_t)NBATCH * NFEAT];              // 32 MB, row-major [B, F]
__device__ __half g_vh[NFIELDS * NFIELDS * NL * FDIM];        // 2 MB, [s][t][l][k]

// ---------------- SMEM layout ----------------
// X buffer: 4 chunks x [256 rows x 128B]  (chunk c holds k in [64c, 64c+64))
// V buffers: 4 chunks x [64 rows x 128B]
#define SM_DKS  0
#define SM_X    1024
#define SM_V1   (1024 + 131072)
#define SM_V2   (1024 + 131072 + 32768)
#define SM_TOTAL (1024 + 196608)  // 197632 B

#define SW128(off) ((off) ^ (((off) >> 3) & 0x70))

static __device__ __forceinline__ uint32_t smem_u32(const void* p) {
    uint32_t a;
    asm("{ .reg .u64 t; cvta.to.shared.u64 t, %1; cvt.u32.u64 %0, t; }" : "=r"(a) : "l"(p));
    return a;
}

#define CP_ASYNC16(dst, src) \
    asm volatile("cp.async.cg.shared.global [%0], [%1], 16;" :: "r"(dst), "l"(src))
#define CP_COMMIT() asm volatile("cp.async.commit_group;" ::: "memory")
#define CP_WAIT0()  asm volatile("cp.async.wait_group 0;" ::: "memory")

static __device__ __forceinline__ void ldmx4(uint32_t addr, uint32_t& r0, uint32_t& r1,
                                             uint32_t& r2, uint32_t& r3) {
    asm volatile("ldmatrix.sync.aligned.m8n8.x4.shared.b16 {%0,%1,%2,%3}, [%4];"
                 : "=r"(r0), "=r"(r1), "=r"(r2), "=r"(r3) : "r"(addr));
}

static __device__ __forceinline__ void mma16816(float* d, uint32_t a0, uint32_t a1,
                                                uint32_t a2, uint32_t a3,
                                                uint32_t b0, uint32_t b1) {
    asm volatile(
        "mma.sync.aligned.m16n8k16.row.col.f32.f16.f16.f32 "
        "{%0,%1,%2,%3}, {%4,%5,%6,%7}, {%8,%9}, {%0,%1,%2,%3};"
        : "+f"(d[0]), "+f"(d[1]), "+f"(d[2]), "+f"(d[3])
        : "r"(a0), "r"(a1), "r"(a2), "r"(a3), "r"(b0), "r"(b1));
}

// unit table: 8 diagonal + 28 unordered pairs (s < t)
__device__ const signed char U_S[36] = {0,1,2,3,4,5,6,7,
    0,0,0,0,0,0,0, 1,1,1,1,1,1, 2,2,2,2,2, 3,3,3,3, 4,4,4, 5,5, 6};
__device__ const signed char U_T[36] = {0,1,2,3,4,5,6,7,
    1,2,3,4,5,6,7, 2,3,4,5,6,7, 3,4,5,6,7, 4,5,6,7, 5,6,7, 6,7, 7};

// ------------------------------------------------------------------
__global__ void k_convert_x(const float* __restrict__ x) {
    size_t i = (size_t)blockIdx.x * blockDim.x + threadIdx.x;
    size_t n2 = (size_t)NBATCH * NFEAT / 2;
    if (i < n2) {
        float2 f = ((const float2*)x)[i];
        ((__half2*)g_xh)[i] = __floats2half2_rn(f.x, f.y);
    }
}

__global__ void k_convert_v(const float* __restrict__ V) {
    int idx = blockIdx.x * blockDim.x + threadIdx.x;  // over 2048*8*64
    if (idx < NFEAT * NFIELDS * NL) {
        int i = idx / (NFIELDS * NL);
        int rest = idx % (NFIELDS * NL);
        int t = rest / NL, l = rest % NL;
        int s = i >> 8, k = i & 255;
        g_vh[(((s * NFIELDS + t) * NL) + l) * FDIM + k] = __float2half_rn(V[idx]);
    }
}

__global__ void k_init_out(const float* __restrict__ b, float* __restrict__ out) {
    int i = blockIdx.x * blockDim.x + threadIdx.x;
    if (i < NBATCH) out[i] = b[0];
}

// ------------------------------------------------------------------
// cp.async tile loaders (SW128, 4 chunks)
static __device__ __forceinline__ void load_x_tile(uint32_t sbuf, const __half* gsrc, int tid) {
    #pragma unroll 4
    for (int idx = tid; idx < ROWT * 32; idx += NTHREADS) {
        int row = idx >> 5, c = idx & 31;
        uint32_t saddr = sbuf + (c >> 3) * 32768 + SW128(row * 128 + (c & 7) * 16);
        const char* gaddr = (const char*)gsrc + (size_t)row * (NFEAT * 2) + c * 16;
        CP_ASYNC16(saddr, gaddr);
    }
}

static __device__ __forceinline__ void load_v_tile(uint32_t sbuf, const __half* gsrc, int tid) {
    #pragma unroll 2
    for (int idx = tid; idx < NL * 32; idx += NTHREADS) {
        int row = idx >> 5, c = idx & 31;
        uint32_t saddr = sbuf + (c >> 3) * 8192 + SW128(row * 128 + (c & 7) * 16);
        const char* gaddr = (const char*)gsrc + row * (FDIM * 2) + c * 16;
        CP_ASYNC16(saddr, gaddr);
    }
}

// Accumulate D[16 rows x 64 cols] fragments: X_tile(warp's 16 rows x 256) @ V_tile^T
static __device__ __forceinline__ void gemm_warp(uint32_t sx, uint32_t sv,
                                                 int wid, int lane, float acc[8][4]) {
    const int arow = wid * 16 + (lane & 15);
    const int akoff8 = (lane >> 4) << 3;                    // 0 or 8 halves
    const int brow_base = ((lane >> 4) << 3) + (lane & 7);  // 0..15 pattern
    const int bkoff8 = ((lane >> 3) & 1) << 3;

    #pragma unroll 2
    for (int kt = 0; kt < 16; ++kt) {
        const int kbase = kt * 16;
        const int chunk = kbase >> 6;
        const int kin = kbase & 63;
        uint32_t a0, a1, a2, a3;
        uint32_t addrA = sx + chunk * 32768 + SW128(arow * 128 + (kin + akoff8) * 2);
        ldmx4(addrA, a0, a1, a2, a3);
        #pragma unroll
        for (int vt = 0; vt < 4; ++vt) {
            const int l0 = vt * 16;
            uint32_t b0, b1, b2, b3;
            uint32_t addrB = sv + chunk * 8192 +
                             SW128((l0 + brow_base) * 128 + (kin + bkoff8) * 2);
            ldmx4(addrB, b0, b1, b2, b3);
            mma16816(acc[2 * vt], a0, a1, a2, a3, b0, b1);
            mma16816(acc[2 * vt + 1], a0, a1, a2, a3, b2, b3);
        }
    }
}

__global__ __launch_bounds__(NTHREADS, 1)
void ffm_main(const float* __restrict__ w, float* __restrict__ out) {
    extern __shared__ char smem[];
    const uint32_t sb = smem_u32(smem);
    const int tid = threadIdx.x;
    const int wid = tid >> 5;
    const int lane = tid & 31;
    const int r0 = blockIdx.x * ROWT;

    float acc_int0 = 0.f, acc_int1 = 0.f;   // rows wid*16 + lane/4 (+8)
    float acc_lin0 = 0.f, acc_lin1 = 0.f;
    float* dks = (float*)(smem + SM_DKS);

    for (int uu = 0; uu < 4; ++uu) {
        const int u = blockIdx.y * 4 + uu;
        const int s = U_S[u], t = U_T[u];
        const bool diag = (s == t);

        // ---- phase A: X_s + V_st (+ V_ts for pairs), async ----
        load_x_tile(sb + SM_X, g_xh + (size_t)r0 * NFEAT + s * FDIM, tid);
        load_v_tile(sb + SM_V1, g_vh + (size_t)((s * NFIELDS + t) * NL) * FDIM, tid);
        if (!diag)
            load_v_tile(sb + SM_V2, g_vh + (size_t)((t * NFIELDS + s) * NL) * FDIM, tid);
        CP_COMMIT();
        CP_WAIT0();
        __syncthreads();

        float accA[8][4];
        #pragma unroll
        for (int n = 0; n < 8; ++n)
            #pragma unroll
            for (int j = 0; j < 4; ++j) accA[n][j] = 0.f;
        gemm_warp(sb + SM_X, sb + SM_V1, wid, lane, accA);

        float p0 = 0.f, p1 = 0.f;
        if (!diag) {
            // ---- phase B: overwrite X buffer with X_t ----
            __syncthreads();  // all warps done reading X_s
            load_x_tile(sb + SM_X, g_xh + (size_t)r0 * NFEAT + t * FDIM, tid);
            CP_COMMIT();
            CP_WAIT0();
            __syncthreads();

            float accB[8][4];
            #pragma unroll
            for (int n = 0; n < 8; ++n)
                #pragma unroll
                for (int j = 0; j < 4; ++j) accB[n][j] = 0.f;
            gemm_warp(sb + SM_X, sb + SM_V2, wid, lane, accB);

            #pragma unroll
            for (int n = 0; n < 8; ++n) {
                p0 += accA[n][0] * accB[n][0] + accA[n][1] * accB[n][1];
                p1 += accA[n][2] * accB[n][2] + accA[n][3] * accB[n][3];
            }
            p0 *= 2.f; p1 *= 2.f;
            p0 += __shfl_xor_sync(0xFFFFFFFFu, p0, 1);
            p0 += __shfl_xor_sync(0xFFFFFFFFu, p0, 2);
            p1 += __shfl_xor_sync(0xFFFFFFFFu, p1, 1);
            p1 += __shfl_xor_sync(0xFFFFFFFFu, p1, 2);
            acc_int0 += p0; acc_int1 += p1;
        } else {
            // q + linear from the SAME fp16 tiles the MMA consumed
            if (tid < FDIM) {
                int k = tid;
                float a = 0.f;
                int chunk = k >> 6, kk = (k & 63) * 2;
                #pragma unroll 8
                for (int l = 0; l < NL; ++l) {
                    float f = __half2float(*(const __half*)(smem + SM_V1 + chunk * 8192 +
                                                            SW128(l * 128 + kk)));
                    a += f * f;
                }
                dks[k] = a;
            }
            __syncthreads();
            const int rloc0 = wid * 16 + (lane >> 2);
            const int rloc1 = rloc0 + 8;
            const int kseg = lane & 3;               // 4 lanes per row: 64 k's each
            const float* wp = w + s * FDIM + kseg * 64;
            float q0 = 0.f, q1 = 0.f, l0 = 0.f, l1 = 0.f;
            #pragma unroll 8
            for (int kk = 0; kk < 64; ++kk) {
                int k = kseg * 64 + kk;
                float dk = dks[k];
                float wv = __ldg(wp + kk);
                float x0 = __half2float(*(const __half*)(smem + SM_X + kseg * 32768 +
                                                         SW128(rloc0 * 128 + kk * 2)));
                float x1 = __half2float(*(const __half*)(smem + SM_X + kseg * 32768 +
                                                         SW128(rloc1 * 128 + kk * 2)));
                q0 += x0 * x0 * dk; l0 += x0 * wv;
                q1 += x1 * x1 * dk; l1 += x1 * wv;
            }
            #pragma unroll
            for (int n = 0; n < 8; ++n) {
                p0 += accA[n][0] * accA[n][0] + accA[n][1] * accA[n][1];
                p1 += accA[n][2] * accA[n][2] + accA[n][3] * accA[n][3];
            }
            p0 -= q0; p1 -= q1;
            p0 += __shfl_xor_sync(0xFFFFFFFFu, p0, 1);
            p0 += __shfl_xor_sync(0xFFFFFFFFu, p0, 2);
            p1 += __shfl_xor_sync(0xFFFFFFFFu, p1, 1);
            p1 += __shfl_xor_sync(0xFFFFFFFFu, p1, 2);
            l0 += __shfl_xor_sync(0xFFFFFFFFu, l0, 1);
            l0 += __shfl_xor_sync(0xFFFFFFFFu, l0, 2);
            l1 += __shfl_xor_sync(0xFFFFFFFFu, l1, 1);
            l1 += __shfl_xor_sync(0xFFFFFFFFu, l1, 2);
            acc_int0 += p0; acc_int1 += p1;
            acc_lin0 += l0; acc_lin1 += l1;
        }
        __syncthreads();   // before next unit's loads overwrite tiles
    }

    if ((lane & 3) == 0) {
        int row = r0 + wid * 16 + (lane >> 2);
        atomicAdd(out + row,      acc_lin0 + 0.25f * acc_int0);
        atomicAdd(out + row + 8,  acc_lin1 + 0.25f * acc_int1);
    }
}

// ------------------------------------------------------------------
extern "C" void kernel_launch(void* const* d_in, const int* in_sizes, int n_in,
                              void* d_out, int out_size) {
    const float* x = (const float*)d_in[0];
    const float* b = (const float*)d_in[1];
    const float* w = (const float*)d_in[2];
    const float* V = (const float*)d_in[3];
    float* out = (float*)d_out;

    cudaFuncSetAttribute(ffm_main, cudaFuncAttributeMaxDynamicSharedMemorySize, SM_TOTAL);

    {
        size_t n2 = (size_t)NBATCH * NFEAT / 2;
        k_convert_x<<<(unsigned)((n2 + 255) / 256), 256>>>(x);
    }
    k_convert_v<<<(NFEAT * NFIELDS * NL + 255) / 256, 256>>>(V);
    k_init_out<<<(NBATCH + 255) / 256, 256>>>(b, out);
    ffm_main<<<dim3(NBATCH / ROWT, 9), NTHREADS, SM_TOTAL>>>(w, out);
}

// round 4
// speedup vs baseline: 1.4465x; 1.0684x over previous
#include <cuda_runtime.h>
#include <cuda_fp16.h>
#include <cstdint>

#define NFEAT   2048
#define NBATCH  8192
#define NFIELDS 8
#define FDIM    256
#define NL      64
#define ROWT    256
#define NTHREADS 512

// fp16 scratch (static device arrays -- no runtime allocation)
__device__ __half g_xh[(size_t)NBATCH * NFEAT];              // 32 MB, row-major [B, F]
__device__ __half g_vh[NFIELDS * NFIELDS * NL * FDIM];        // 2 MB, [s][t][l][k]

// ---------------- SMEM layout ----------------
// XA/XB: k-half buffers, each 2 chunks x [256 rows x 128B] = 64KB
//   (global k-chunk c in 0..3 -> buffer c>>1, local chunk c&1)
// V1/V2: 4 chunks x [64 rows x 128B] = 32KB each
#define SM_DKS  0
#define SM_XA   1024
#define SM_XB   (1024 + 65536)
#define SM_V1   (1024 + 131072)
#define SM_V2   (1024 + 131072 + 32768)
#define SM_TOTAL (1024 + 196608)  // 197632 B

#define SW128(off) ((off) ^ (((off) >> 3) & 0x70))

static __device__ __forceinline__ uint32_t smem_u32(const void* p) {
    uint32_t a;
    asm("{ .reg .u64 t; cvta.to.shared.u64 t, %1; cvt.u32.u64 %0, t; }" : "=r"(a) : "l"(p));
    return a;
}

#define CP_ASYNC16(dst, src) \
    asm volatile("cp.async.cg.shared.global [%0], [%1], 16;" :: "r"(dst), "l"(src))
#define CP_COMMIT() asm volatile("cp.async.commit_group;" ::: "memory")
#define CP_WAIT0()  asm volatile("cp.async.wait_group 0;" ::: "memory")
#define CP_WAIT1()  asm volatile("cp.async.wait_group 1;" ::: "memory")

static __device__ __forceinline__ void ldmx4(uint32_t addr, uint32_t& r0, uint32_t& r1,
                                             uint32_t& r2, uint32_t& r3) {
    asm volatile("ldmatrix.sync.aligned.m8n8.x4.shared.b16 {%0,%1,%2,%3}, [%4];"
                 : "=r"(r0), "=r"(r1), "=r"(r2), "=r"(r3) : "r"(addr));
}

static __device__ __forceinline__ void mma16816(float* d, uint32_t a0, uint32_t a1,
                                                uint32_t a2, uint32_t a3,
                                                uint32_t b0, uint32_t b1) {
    asm volatile(
        "mma.sync.aligned.m16n8k16.row.col.f32.f16.f16.f32 "
        "{%0,%1,%2,%3}, {%4,%5,%6,%7}, {%8,%9}, {%0,%1,%2,%3};"
        : "+f"(d[0]), "+f"(d[1]), "+f"(d[2]), "+f"(d[3])
        : "r"(a0), "r"(a1), "r"(a2), "r"(a3), "r"(b0), "r"(b1));
}

// unit table: 8 diagonal + 28 unordered pairs (s < t)
__device__ const signed char U_S[36] = {0,1,2,3,4,5,6,7,
    0,0,0,0,0,0,0, 1,1,1,1,1,1, 2,2,2,2,2, 3,3,3,3, 4,4,4, 5,5, 6};
__device__ const signed char U_T[36] = {0,1,2,3,4,5,6,7,
    1,2,3,4,5,6,7, 2,3,4,5,6,7, 3,4,5,6,7, 4,5,6,7, 5,6,7, 6,7, 7};

// ------------------------------------------------------------------
__global__ void k_convert_x(const float* __restrict__ x) {
    size_t i = (size_t)blockIdx.x * blockDim.x + threadIdx.x;  // 8 floats each
    size_t n8 = (size_t)NBATCH * NFEAT / 8;
    if (i < n8) {
        const float4* src = (const float4*)x;
        float4 f0 = src[2 * i], f1 = src[2 * i + 1];
        __half2 h0 = __floats2half2_rn(f0.x, f0.y);
        __half2 h1 = __floats2half2_rn(f0.z, f0.w);
        __half2 h2 = __floats2half2_rn(f1.x, f1.y);
        __half2 h3 = __floats2half2_rn(f1.z, f1.w);
        uint4 o;
        o.x = *(uint32_t*)&h0; o.y = *(uint32_t*)&h1;
        o.z = *(uint32_t*)&h2; o.w = *(uint32_t*)&h3;
        ((uint4*)g_xh)[i] = o;
    }
}

__global__ void k_convert_v(const float* __restrict__ V) {
    int idx = blockIdx.x * blockDim.x + threadIdx.x;  // over 2048*8*64
    if (idx < NFEAT * NFIELDS * NL) {
        int i = idx / (NFIELDS * NL);
        int rest = idx % (NFIELDS * NL);
        int t = rest / NL, l = rest % NL;
        int s = i >> 8, k = i & 255;
        g_vh[(((s * NFIELDS + t) * NL) + l) * FDIM + k] = __float2half_rn(V[idx]);
    }
}

__global__ void k_init_out(const float* __restrict__ b, float* __restrict__ out) {
    int i = blockIdx.x * blockDim.x + threadIdx.x;
    if (i < NBATCH) out[i] = b[0];
}

// ------------------------------------------------------------------
// load one k-half of the X tile (256 rows x 128 k): 4096 x 16B, 8 per thread
static __device__ __forceinline__ void load_x_half(uint32_t sbuf, const __half* gsrc, int tid) {
    #pragma unroll
    for (int it = 0; it < 8; ++it) {
        int idx = tid + it * NTHREADS;          // 0..4095
        int row = idx >> 4, c = idx & 15;       // 16 x 16B per 256B half-row
        uint32_t saddr = sbuf + (c >> 3) * 32768 + SW128(row * 128 + (c & 7) * 16);
        const char* gaddr = (const char*)gsrc + (size_t)row * (NFEAT * 2) + c * 16;
        CP_ASYNC16(saddr, gaddr);
    }
}

// load one V tile (64 rows x 256 k): 2048 x 16B, 4 per thread
static __device__ __forceinline__ void load_v_tile(uint32_t sbuf, const __half* gsrc, int tid) {
    #pragma unroll
    for (int it = 0; it < 4; ++it) {
        int idx = tid + it * NTHREADS;
        int row = idx >> 5, c = idx & 31;
        uint32_t saddr = sbuf + (c >> 3) * 8192 + SW128(row * 128 + (c & 7) * 16);
        const char* gaddr = (const char*)gsrc + row * (FDIM * 2) + c * 16;
        CP_ASYNC16(saddr, gaddr);
    }
}

// Half-K GEMM: acc += X_half(warp's 16 rows x 128k) @ V[chunks cpair*2..cpair*2+1]^T
static __device__ __forceinline__ void gemm_half(uint32_t sxh, uint32_t sv, int cpair,
                                                 int wid, int lane, float acc[8][4]) {
    const int arow = wid * 16 + (lane & 15);
    const int akoff = ((lane >> 4) << 3) * 2;               // 0 or 16 bytes
    const int brow_base = ((lane >> 4) << 3) + (lane & 7);
    const int bkoff = (((lane >> 3) & 1) << 3) * 2;         // 0 or 16 bytes
    const uint32_t svp = sv + cpair * 16384;

    #pragma unroll
    for (int lc = 0; lc < 2; ++lc) {
        #pragma unroll
        for (int k4 = 0; k4 < 4; ++k4) {
            const int kinb = k4 * 32;                        // byte offset of k-step
            uint32_t a0, a1, a2, a3;
            ldmx4(sxh + lc * 32768 + SW128(arow * 128 + kinb + akoff), a0, a1, a2, a3);
            #pragma unroll
            for (int vt = 0; vt < 4; ++vt) {
                uint32_t b0, b1, b2, b3;
                ldmx4(svp + lc * 8192 +
                      SW128((vt * 16 + brow_base) * 128 + kinb + bkoff), b0, b1, b2, b3);
                mma16816(acc[2 * vt],     a0, a1, a2, a3, b0, b1);
                mma16816(acc[2 * vt + 1], a0, a1, a2, a3, b2, b3);
            }
        }
    }
}

__global__ __launch_bounds__(NTHREADS, 1)
void ffm_main(const float* __restrict__ w, float* __restrict__ out) {
    extern __shared__ char smem[];
    const uint32_t sb = smem_u32(smem);
    const uint32_t XA = sb + SM_XA, XB = sb + SM_XB, V1 = sb + SM_V1, V2 = sb + SM_V2;
    const int tid = threadIdx.x;
    const int wid = tid >> 5;
    const int lane = tid & 31;
    const int r0 = blockIdx.x * ROWT;

    float acc_int0 = 0.f, acc_int1 = 0.f;   // rows wid*16 + lane/4 (+8)
    float acc_lin0 = 0.f, acc_lin1 = 0.f;
    float* dks = (float*)(smem + SM_DKS);

    for (int uu = 0; uu < 4; ++uu) {
        const int u = blockIdx.y * 4 + uu;
        const int s = U_S[u], t = U_T[u];
        const bool diag = (s == t);
        const __half* xs = g_xh + (size_t)r0 * NFEAT + s * FDIM;
        const __half* xt = g_xh + (size_t)r0 * NFEAT + t * FDIM;

        // g1: XA <- X_s half0, V1 (, V2)    g2: XB <- X_s half1
        load_x_half(XA, xs, tid);
        load_v_tile(V1, g_vh + (size_t)((s * NFIELDS + t) * NL) * FDIM, tid);
        if (!diag)
            load_v_tile(V2, g_vh + (size_t)((t * NFIELDS + s) * NL) * FDIM, tid);
        CP_COMMIT();
        load_x_half(XB, xs + 128, tid);
        CP_COMMIT();

        float accA[8][4];
        #pragma unroll
        for (int n = 0; n < 8; ++n)
            #pragma unroll
            for (int j = 0; j < 4; ++j) accA[n][j] = 0.f;

        CP_WAIT1(); __syncthreads();               // g1 done
        gemm_half(XA, V1, 0, wid, lane, accA);

        float p0 = 0.f, p1 = 0.f;
        if (!diag) {
            float accB[8][4];
            #pragma unroll
            for (int n = 0; n < 8; ++n)
                #pragma unroll
                for (int j = 0; j < 4; ++j) accB[n][j] = 0.f;

            __syncthreads();                        // XA free
            load_x_half(XA, xt, tid); CP_COMMIT();  // g3 (overlaps next GEMM)
            CP_WAIT1(); __syncthreads();            // g2 done
            gemm_half(XB, V1, 1, wid, lane, accA);

            __syncthreads();                        // XB free
            load_x_half(XB, xt + 128, tid); CP_COMMIT();  // g4
            CP_WAIT1(); __syncthreads();            // g3 done
            gemm_half(XA, V2, 0, wid, lane, accB);

            CP_WAIT0(); __syncthreads();            // g4 done
            gemm_half(XB, V2, 1, wid, lane, accB);

            #pragma unroll
            for (int n = 0; n < 8; ++n) {
                p0 += accA[n][0] * accB[n][0] + accA[n][1] * accB[n][1];
                p1 += accA[n][2] * accB[n][2] + accA[n][3] * accB[n][3];
            }
            p0 *= 2.f; p1 *= 2.f;
            p0 += __shfl_xor_sync(0xFFFFFFFFu, p0, 1);
            p0 += __shfl_xor_sync(0xFFFFFFFFu, p0, 2);
            p1 += __shfl_xor_sync(0xFFFFFFFFu, p1, 1);
            p1 += __shfl_xor_sync(0xFFFFFFFFu, p1, 2);
            acc_int0 += p0; acc_int1 += p1;
        } else {
            CP_WAIT0(); __syncthreads();            // g2 done
            gemm_half(XB, V1, 1, wid, lane, accA);

            // q + linear from the SAME fp16 tiles the MMA consumed
            if (tid < FDIM) {
                int k = tid;
                float a = 0.f;
                int chunk = k >> 6, kk = (k & 63) * 2;
                #pragma unroll 8
                for (int l = 0; l < NL; ++l) {
                    float f = __half2float(*(const __half*)(smem + SM_V1 + chunk * 8192 +
                                                            SW128(l * 128 + kk)));
                    a += f * f;
                }
                dks[k] = a;
            }
            __syncthreads();
            const int rloc0 = wid * 16 + (lane >> 2);
            const int rloc1 = rloc0 + 8;
            const int kseg = lane & 3;               // global chunk index
            const char* xsm = smem + (kseg < 2 ? SM_XA : SM_XB) + (kseg & 1) * 32768;
            const float* wp = w + s * FDIM + kseg * 64;
            float q0 = 0.f, q1 = 0.f, l0 = 0.f, l1 = 0.f;
            #pragma unroll 8
            for (int kk = 0; kk < 64; ++kk) {
                int k = kseg * 64 + kk;
                float dk = dks[k];
                float wv = __ldg(wp + kk);
                float x0 = __half2float(*(const __half*)(xsm + SW128(rloc0 * 128 + kk * 2)));
                float x1 = __half2float(*(const __half*)(xsm + SW128(rloc1 * 128 + kk * 2)));
                q0 += x0 * x0 * dk; l0 += x0 * wv;
                q1 += x1 * x1 * dk; l1 += x1 * wv;
            }
            #pragma unroll
            for (int n = 0; n < 8; ++n) {
                p0 += accA[n][0] * accA[n][0] + accA[n][1] * accA[n][1];
                p1 += accA[n][2] * accA[n][2] + accA[n][3] * accA[n][3];
            }
            p0 -= q0; p1 -= q1;
            p0 += __shfl_xor_sync(0xFFFFFFFFu, p0, 1);
            p0 += __shfl_xor_sync(0xFFFFFFFFu, p0, 2);
            p1 += __shfl_xor_sync(0xFFFFFFFFu, p1, 1);
            p1 += __shfl_xor_sync(0xFFFFFFFFu, p1, 2);
            l0 += __shfl_xor_sync(0xFFFFFFFFu, l0, 1);
            l0 += __shfl_xor_sync(0xFFFFFFFFu, l0, 2);
            l1 += __shfl_xor_sync(0xFFFFFFFFu, l1, 1);
            l1 += __shfl_xor_sync(0xFFFFFFFFu, l1, 2);
            acc_int0 += p0; acc_int1 += p1;
            acc_lin0 += l0; acc_lin1 += l1;
        }
        __syncthreads();   // before next unit's loads overwrite tiles
    }

    if ((lane & 3) == 0) {
        int row = r0 + wid * 16 + (lane >> 2);
        atomicAdd(out + row,      acc_lin0 + 0.25f * acc_int0);
        atomicAdd(out + row + 8,  acc_lin1 + 0.25f * acc_int1);
    }
}

// ------------------------------------------------------------------
extern "C" void kernel_launch(void* const* d_in, const int* in_sizes, int n_in,
                              void* d_out, int out_size) {
    const float* x = (const float*)d_in[0];
    const float* b = (const float*)d_in[1];
    const float* w = (const float*)d_in[2];
    const float* V = (const float*)d_in[3];
    float* out = (float*)d_out;

    cudaFuncSetAttribute(ffm_main, cudaFuncAttributeMaxDynamicSharedMemorySize, SM_TOTAL);

    {
        size_t n8 = (size_t)NBATCH * NFEAT / 8;
        k_convert_x<<<(unsigned)((n8 + 255) / 256), 256>>>(x);
    }
    k_convert_v<<<(NFEAT * NFIELDS * NL + 255) / 256, 256>>>(V);
    k_init_out<<<(NBATCH + 255) / 256, 256>>>(b, out);
    ffm_main<<<dim3(NBATCH / ROWT, 9), NTHREADS, SM_TOTAL>>>(w, out);
}

// round 5
// speedup vs baseline: 1.7284x; 1.1949x over previous
#include <cuda_runtime.h>
#include <cuda_fp16.h>
#include <cstdint>

#define NFEAT   2048
#define NBATCH  8192
#define NFIELDS 8
#define FDIM    256
#define NL      64
#define ROWT    128
#define NTHREADS 256

// fp16 scratch (static device arrays -- no runtime allocation)
__device__ __half g_xh[(size_t)NBATCH * NFEAT];              // 32 MB, row-major [B, F]
__device__ __half g_vh[NFIELDS * NFIELDS * NL * FDIM];        // 2 MB, [s][t][l][k]

// ---------------- SMEM layout (97 KB -> 2 CTAs/SM) ----------------
// XA/XB: k-half X buffers, 2 chunks x [128 rows x 128B] = 32 KB each
// VA/VB: k-half V buffers, 2 chunks x [64 rows x 128B] = 16 KB each
#define SM_DKS  0
#define SM_XA   1024
#define SM_XB   (SM_XA + 32768)
#define SM_VA   (SM_XB + 32768)
#define SM_VB   (SM_VA + 16384)
#define SM_TOTAL (SM_VB + 16384)   // 99328 B

#define SW128(off) ((off) ^ (((off) >> 3) & 0x70))

static __device__ __forceinline__ uint32_t smem_u32(const void* p) {
    uint32_t a;
    asm("{ .reg .u64 t; cvta.to.shared.u64 t, %1; cvt.u32.u64 %0, t; }" : "=r"(a) : "l"(p));
    return a;
}

#define CP_ASYNC16(dst, src) \
    asm volatile("cp.async.cg.shared.global [%0], [%1], 16;" :: "r"(dst), "l"(src))
#define CP_COMMIT() asm volatile("cp.async.commit_group;" ::: "memory")
#define CP_WAIT0()  asm volatile("cp.async.wait_group 0;" ::: "memory")
#define CP_WAIT1()  asm volatile("cp.async.wait_group 1;" ::: "memory")

static __device__ __forceinline__ void ldmx4(uint32_t addr, uint32_t& r0, uint32_t& r1,
                                             uint32_t& r2, uint32_t& r3) {
    asm volatile("ldmatrix.sync.aligned.m8n8.x4.shared.b16 {%0,%1,%2,%3}, [%4];"
                 : "=r"(r0), "=r"(r1), "=r"(r2), "=r"(r3) : "r"(addr));
}

static __device__ __forceinline__ void mma16816(float* d, uint32_t a0, uint32_t a1,
                                                uint32_t a2, uint32_t a3,
                                                uint32_t b0, uint32_t b1) {
    asm volatile(
        "mma.sync.aligned.m16n8k16.row.col.f32.f16.f16.f32 "
        "{%0,%1,%2,%3}, {%4,%5,%6,%7}, {%8,%9}, {%0,%1,%2,%3};"
        : "+f"(d[0]), "+f"(d[1]), "+f"(d[2]), "+f"(d[3])
        : "r"(a0), "r"(a1), "r"(a2), "r"(a3), "r"(b0), "r"(b1));
}

// unit table: 8 diagonal + 28 unordered pairs (s < t)
__device__ const signed char U_S[36] = {0,1,2,3,4,5,6,7,
    0,0,0,0,0,0,0, 1,1,1,1,1,1, 2,2,2,2,2, 3,3,3,3, 4,4,4, 5,5, 6};
__device__ const signed char U_T[36] = {0,1,2,3,4,5,6,7,
    1,2,3,4,5,6,7, 2,3,4,5,6,7, 3,4,5,6,7, 4,5,6,7, 5,6,7, 6,7, 7};

// ------------------------------------------------------------------
__global__ void k_convert_x(const float* __restrict__ x) {
    size_t i = (size_t)blockIdx.x * blockDim.x + threadIdx.x;  // 8 floats each
    size_t n8 = (size_t)NBATCH * NFEAT / 8;
    if (i < n8) {
        const float4* src = (const float4*)x;
        float4 f0 = src[2 * i], f1 = src[2 * i + 1];
        __half2 h0 = __floats2half2_rn(f0.x, f0.y);
        __half2 h1 = __floats2half2_rn(f0.z, f0.w);
        __half2 h2 = __floats2half2_rn(f1.x, f1.y);
        __half2 h3 = __floats2half2_rn(f1.z, f1.w);
        uint4 o;
        o.x = *(uint32_t*)&h0; o.y = *(uint32_t*)&h1;
        o.z = *(uint32_t*)&h2; o.w = *(uint32_t*)&h3;
        ((uint4*)g_xh)[i] = o;
    }
}

__global__ void k_convert_v(const float* __restrict__ V) {
    int idx = blockIdx.x * blockDim.x + threadIdx.x;  // over 2048*8*64
    if (idx < NFEAT * NFIELDS * NL) {
        int i = idx / (NFIELDS * NL);
        int rest = idx % (NFIELDS * NL);
        int t = rest / NL, l = rest % NL;
        int s = i >> 8, k = i & 255;
        g_vh[(((s * NFIELDS + t) * NL) + l) * FDIM + k] = __float2half_rn(V[idx]);
    }
}

__global__ void k_init_out(const float* __restrict__ b, float* __restrict__ out) {
    int i = blockIdx.x * blockDim.x + threadIdx.x;
    if (i < NBATCH) out[i] = b[0];
}

// ------------------------------------------------------------------
// X k-half: 128 rows x 128 k = 32KB = 2048 x 16B; 256 thr -> 8 iters
static __device__ __forceinline__ void load_x_half(uint32_t sbuf, const __half* gsrc, int tid) {
    #pragma unroll
    for (int it = 0; it < 8; ++it) {
        int idx = tid + it * NTHREADS;          // 0..2047
        int row = idx >> 4, c = idx & 15;       // 16 x 16B per 256B half-row
        uint32_t saddr = sbuf + (c >> 3) * 16384 + SW128(row * 128 + (c & 7) * 16);
        const char* gaddr = (const char*)gsrc + (size_t)row * (NFEAT * 2) + c * 16;
        CP_ASYNC16(saddr, gaddr);
    }
}

// V k-half: 64 rows x 128 k = 16KB = 1024 x 16B; 256 thr -> 4 iters
static __device__ __forceinline__ void load_v_half(uint32_t sbuf, const __half* gsrc, int tid) {
    #pragma unroll
    for (int it = 0; it < 4; ++it) {
        int idx = tid + it * NTHREADS;
        int row = idx >> 4, c = idx & 15;
        uint32_t saddr = sbuf + (c >> 3) * 8192 + SW128(row * 128 + (c & 7) * 16);
        const char* gaddr = (const char*)gsrc + row * (FDIM * 2) + c * 16;
        CP_ASYNC16(saddr, gaddr);
    }
}

// Half-K GEMM: acc += X_half(warp's 16 rows x 128k) @ V_half^T   (n = 64)
static __device__ __forceinline__ void gemm_half(uint32_t sxh, uint32_t svh,
                                                 int wid, int lane, float acc[8][4]) {
    const int arow = wid * 16 + (lane & 15);
    const int akoff = ((lane >> 4) << 3) * 2;               // 0 or 16 bytes
    const int brow_base = ((lane >> 4) << 3) + (lane & 7);
    const int bkoff = (((lane >> 3) & 1) << 3) * 2;         // 0 or 16 bytes

    #pragma unroll
    for (int lc = 0; lc < 2; ++lc) {
        #pragma unroll
        for (int k4 = 0; k4 < 4; ++k4) {
            const int kinb = k4 * 32;                        // byte offset of k-step
            uint32_t a0, a1, a2, a3;
            ldmx4(sxh + lc * 16384 + SW128(arow * 128 + kinb + akoff), a0, a1, a2, a3);
            #pragma unroll
            for (int vt = 0; vt < 4; ++vt) {
                uint32_t b0, b1, b2, b3;
                ldmx4(svh + lc * 8192 +
                      SW128((vt * 16 + brow_base) * 128 + kinb + bkoff), b0, b1, b2, b3);
                mma16816(acc[2 * vt],     a0, a1, a2, a3, b0, b1);
                mma16816(acc[2 * vt + 1], a0, a1, a2, a3, b2, b3);
            }
        }
    }
}

__global__ __launch_bounds__(NTHREADS, 2)
void ffm_main(const float* __restrict__ w, float* __restrict__ out) {
    extern __shared__ char smem[];
    const uint32_t sb = smem_u32(smem);
    const uint32_t XA = sb + SM_XA, XB = sb + SM_XB, VA = sb + SM_VA, VB = sb + SM_VB;
    const int tid = threadIdx.x;
    const int wid = tid >> 5;
    const int lane = tid & 31;
    const int r0 = blockIdx.x * ROWT;

    float acc_int0 = 0.f, acc_int1 = 0.f;   // rows wid*16 + lane/4 (+8)
    float acc_lin0 = 0.f, acc_lin1 = 0.f;
    float* dks = (float*)(smem + SM_DKS);

    for (int uu = 0; uu < 4; ++uu) {
        const int u = blockIdx.y * 4 + uu;
        const int s = U_S[u], t = U_T[u];
        const bool diag = (s == t);
        const __half* xs = g_xh + (size_t)r0 * NFEAT + s * FDIM;
        const __half* xt = g_xh + (size_t)r0 * NFEAT + t * FDIM;
        const __half* vst = g_vh + (size_t)((s * NFIELDS + t) * NL) * FDIM;
        const __half* vts = g_vh + (size_t)((t * NFIELDS + s) * NL) * FDIM;

        // g1: XA<-Xs.h0, VA<-Vst.h0    g2: XB<-Xs.h1, VB<-Vst.h1
        load_x_half(XA, xs, tid);
        load_v_half(VA, vst, tid);
        CP_COMMIT();
        load_x_half(XB, xs + 128, tid);
        load_v_half(VB, vst + 128, tid);
        CP_COMMIT();

        float accA[8][4];
        #pragma unroll
        for (int n = 0; n < 8; ++n)
            #pragma unroll
            for (int j = 0; j < 4; ++j) accA[n][j] = 0.f;

        CP_WAIT1(); __syncthreads();               // g1 done
        gemm_half(XA, VA, wid, lane, accA);

        float p0 = 0.f, p1 = 0.f;
        if (!diag) {
            float accB[8][4];
            #pragma unroll
            for (int n = 0; n < 8; ++n)
                #pragma unroll
                for (int j = 0; j < 4; ++j) accB[n][j] = 0.f;

            __syncthreads();                        // XA/VA free
            load_x_half(XA, xt, tid);               // g3: Xt.h0, Vts.h0
            load_v_half(VA, vts, tid);
            CP_COMMIT();
            CP_WAIT1(); __syncthreads();            // g2 done
            gemm_half(XB, VB, wid, lane, accA);     // (g3 streams underneath)

            __syncthreads();                        // XB/VB free
            load_x_half(XB, xt + 128, tid);         // g4: Xt.h1, Vts.h1
            load_v_half(VB, vts + 128, tid);
            CP_COMMIT();
            CP_WAIT1(); __syncthreads();            // g3 done
            gemm_half(XA, VA, wid, lane, accB);     // (g4 streams underneath)

            CP_WAIT0(); __syncthreads();            // g4 done
            gemm_half(XB, VB, wid, lane, accB);

            #pragma unroll
            for (int n = 0; n < 8; ++n) {
                p0 += accA[n][0] * accB[n][0] + accA[n][1] * accB[n][1];
                p1 += accA[n][2] * accB[n][2] + accA[n][3] * accB[n][3];
            }
            p0 *= 2.f; p1 *= 2.f;
            p0 += __shfl_xor_sync(0xFFFFFFFFu, p0, 1);
            p0 += __shfl_xor_sync(0xFFFFFFFFu, p0, 2);
            p1 += __shfl_xor_sync(0xFFFFFFFFu, p1, 1);
            p1 += __shfl_xor_sync(0xFFFFFFFFu, p1, 2);
            acc_int0 += p0; acc_int1 += p1;
        } else {
            CP_WAIT0(); __syncthreads();            // g2 done
            gemm_half(XB, VB, wid, lane, accA);

            // q + linear from the SAME fp16 tiles the MMA consumed
            if (tid < FDIM) {
                int k = tid;
                int chunk = k >> 6;                  // global chunk 0..3
                const char* vsm = smem + (chunk < 2 ? SM_VA : SM_VB) + (chunk & 1) * 8192;
                int kk = (k & 63) * 2;
                float a = 0.f;
                #pragma unroll 8
                for (int l = 0; l < NL; ++l) {
                    float f = __half2float(*(const __half*)(vsm + SW128(l * 128 + kk)));
                    a += f * f;
                }
                dks[k] = a;
            }
            __syncthreads();
            const int rloc0 = wid * 16 + (lane >> 2);
            const int rloc1 = rloc0 + 8;
            const int kseg = lane & 3;               // global chunk index
            const char* xsm = smem + (kseg < 2 ? SM_XA : SM_XB) + (kseg & 1) * 16384;
            const float* wp = w + s * FDIM + kseg * 64;
            float q0 = 0.f, q1 = 0.f, l0 = 0.f, l1 = 0.f;
            #pragma unroll 8
            for (int kk = 0; kk < 64; ++kk) {
                int k = kseg * 64 + kk;
                float dk = dks[k];
                float wv = __ldg(wp + kk);
                float x0 = __half2float(*(const __half*)(xsm + SW128(rloc0 * 128 + kk * 2)));
                float x1 = __half2float(*(const __half*)(xsm + SW128(rloc1 * 128 + kk * 2)));
                q0 += x0 * x0 * dk; l0 += x0 * wv;
                q1 += x1 * x1 * dk; l1 += x1 * wv;
            }
            #pragma unroll
            for (int n = 0; n < 8; ++n) {
                p0 += accA[n][0] * accA[n][0] + accA[n][1] * accA[n][1];
                p1 += accA[n][2] * accA[n][2] + accA[n][3] * accA[n][3];
            }
            p0 -= q0; p1 -= q1;
            p0 += __shfl_xor_sync(0xFFFFFFFFu, p0, 1);
            p0 += __shfl_xor_sync(0xFFFFFFFFu, p0, 2);
            p1 += __shfl_xor_sync(0xFFFFFFFFu, p1, 1);
            p1 += __shfl_xor_sync(0xFFFFFFFFu, p1, 2);
            l0 += __shfl_xor_sync(0xFFFFFFFFu, l0, 1);
            l0 += __shfl_xor_sync(0xFFFFFFFFu, l0, 2);
            l1 += __shfl_xor_sync(0xFFFFFFFFu, l1, 1);
            l1 += __shfl_xor_sync(0xFFFFFFFFu, l1, 2);
            acc_int0 += p0; acc_int1 += p1;
            acc_lin0 += l0; acc_lin1 += l1;
        }
        __syncthreads();   // before next unit's loads overwrite tiles
    }

    if ((lane & 3) == 0) {
        int row = r0 + wid * 16 + (lane >> 2);
        atomicAdd(out + row,      acc_lin0 + 0.25f * acc_int0);
        atomicAdd(out + row + 8,  acc_lin1 + 0.25f * acc_int1);
    }
}

// ------------------------------------------------------------------
extern "C" void kernel_launch(void* const* d_in, const int* in_sizes, int n_in,
                              void* d_out, int out_size) {
    const float* x = (const float*)d_in[0];
    const float* b = (const float*)d_in[1];
    const float* w = (const float*)d_in[2];
    const float* V = (const float*)d_in[3];
    float* out = (float*)d_out;

    cudaFuncSetAttribute(ffm_main, cudaFuncAttributeMaxDynamicSharedMemorySize, SM_TOTAL);

    {
        size_t n8 = (size_t)NBATCH * NFEAT / 8;
        k_convert_x<<<(unsigned)((n8 + 255) / 256), 256>>>(x);
    }
    k_convert_v<<<(NFEAT * NFIELDS * NL + 255) / 256, 256>>>(V);
    k_init_out<<<(NBATCH + 255) / 256, 256>>>(b, out);
    ffm_main<<<dim3(NBATCH / ROWT, 9), NTHREADS, SM_TOTAL>>>(w, out);
}